// round 6
// baseline (speedup 1.0000x reference)
#include <cuda_runtime.h>
#include <cuda_fp16.h>
#include <cuda_bf16.h>

#define NN 50000
#define NE 800000
#define DD 128

// ---------------- scratch (device globals; no allocation) --------------------
__device__ int    g_is64;                   // 1 if edge_index is int64, else int32
__device__ int    g_cnt[NN];                // edge count per row (no self-loop)
__device__ int    g_off[NN];                // CSR row start
__device__ int    g_cur[NN];                // scatter cursor
__device__ int    g_col[NE];                // CSR column indices
__device__ float  g_dinv[NN];
__device__ float  g_Wt[DD * DD];            // W1^T : Wt[k*128 + o]
__device__ float4 g_support[NN * DD / 4];   // x @ W1^T + b1 (fp32, exact)
__device__ uint2  g_ph[NN * 32];            // half2x2: dinv[n]*support[n] per lane
__device__ float  g_s[NN];                  // layer-2 scalar per node (incl b2)
__device__ float  g_ds[NN];                 // dinv[n] * s[n]

// robust index fetch: which=0 rows, which=1 cols
__device__ __forceinline__ int get_idx(const void* ei, int which, int e) {
    if (g_is64) return (int)((const long long*)ei)[(size_t)which * NE + e];
    return ((const int*)ei)[(size_t)which * NE + e];
}

// ---------------- dtype detect + cnt init (fused) -----------------------------
__global__ void __launch_bounds__(256) k_pre(const int* __restrict__ w) {
    int n = blockIdx.x * blockDim.x + threadIdx.x;
    if (n < NN) g_cnt[n] = 0;
    if (blockIdx.x == 0) {
        __shared__ int sor[256];
        int t = threadIdx.x, acc = 0;
        for (int i = t; i < 4096; i += 256) acc |= w[2 * i + 1];
        sor[t] = acc;
        __syncthreads();
        for (int d = 128; d; d >>= 1) { if (t < d) sor[t] |= sor[t + d]; __syncthreads(); }
        if (t == 0) g_is64 = (sor[0] == 0) ? 1 : 0;   // int64 -> odd words all 0
    }
}

__global__ void k_hist(const void* __restrict__ ei) {
    int e = blockIdx.x * blockDim.x + threadIdx.x;
    if (e < NE) atomicAdd(&g_cnt[get_idx(ei, 0, e)], 1);
}

// single block: exclusive scan of g_cnt -> g_off,g_cur ; also dinv
__global__ void __launch_bounds__(1024) k_scan() {
    __shared__ int ssum[1024];
    const int CH = (NN + 1023) / 1024;           // 49
    int t = threadIdx.x;
    int lo = t * CH, hi = min(lo + CH, NN);
    int s = 0;
    for (int i = lo; i < hi; i++) s += g_cnt[i];
    ssum[t] = s;
    __syncthreads();
    for (int d = 1; d < 1024; d <<= 1) {
        int v = (t >= d) ? ssum[t - d] : 0;
        __syncthreads();
        ssum[t] += v;
        __syncthreads();
    }
    int excl = (t == 0) ? 0 : ssum[t - 1];
    for (int i = lo; i < hi; i++) {
        int c = g_cnt[i];
        g_off[i] = excl;
        g_cur[i] = excl;
        g_dinv[i] = rsqrtf((float)(c + 1));      // +1 self-loop
        excl += c;
    }
}

__global__ void k_scatter(const void* __restrict__ ei) {
    int e = blockIdx.x * blockDim.x + threadIdx.x;
    if (e < NE) {
        int r = get_idx(ei, 0, e);
        int pos = atomicAdd(&g_cur[r], 1);
        g_col[pos] = get_idx(ei, 1, e);
    }
}

__global__ void k_transpose(const float* __restrict__ W1) {
    int idx = blockIdx.x * blockDim.x + threadIdx.x;
    if (idx < DD * DD) {
        int o = idx >> 7, k = idx & 127;
        g_Wt[k * DD + o] = W1[idx];
    }
}

// ---------------- GEMM1: support = x @ W1^T + b1 ------------------------------
// 8 warps/block; warp handles 8 nodes; lane owns features 4*lane..4*lane+3
// epilogue also writes g_ph[n] = half(dinv[n]*support[n])
__global__ void __launch_bounds__(256) k_gemm1(const float* __restrict__ x,
                                               const float* __restrict__ b1) {
    __shared__ float xs[8 * 8 * DD];   // 32 KB
    int tid = threadIdx.x, lane = tid & 31, w = tid >> 5;
    int base = blockIdx.x * 64 + w * 8;
    float* xw = xs + w * 8 * DD;

    #pragma unroll
    for (int m = 0; m < 8; m++) {
        int n = base + m;
        float4 v = make_float4(0.f, 0.f, 0.f, 0.f);
        if (n < NN) v = ((const float4*)x)[n * 32 + lane];
        ((float4*)(xw + m * DD))[lane] = v;
    }
    __syncwarp();

    float4 bb = ((const float4*)b1)[lane];
    float4 acc[8];
    #pragma unroll
    for (int m = 0; m < 8; m++) acc[m] = bb;

    const float4* Wt4 = (const float4*)g_Wt;
    #pragma unroll 2
    for (int k = 0; k < DD; k += 4) {
        float4 wv0 = __ldg(&Wt4[(k + 0) * 32 + lane]);   // L1-resident
        float4 wv1 = __ldg(&Wt4[(k + 1) * 32 + lane]);
        float4 wv2 = __ldg(&Wt4[(k + 2) * 32 + lane]);
        float4 wv3 = __ldg(&Wt4[(k + 3) * 32 + lane]);
        #pragma unroll
        for (int m = 0; m < 8; m++) {
            float4 xv = ((const float4*)(xw + m * DD))[k >> 2];  // LDS.128
            acc[m].x += wv0.x * xv.x + wv1.x * xv.y + wv2.x * xv.z + wv3.x * xv.w;
            acc[m].y += wv0.y * xv.x + wv1.y * xv.y + wv2.y * xv.z + wv3.y * xv.w;
            acc[m].z += wv0.z * xv.x + wv1.z * xv.y + wv2.z * xv.z + wv3.z * xv.w;
            acc[m].w += wv0.w * xv.x + wv1.w * xv.y + wv2.w * xv.z + wv3.w * xv.w;
        }
    }

    #pragma unroll
    for (int m = 0; m < 8; m++) {
        int n = base + m;
        if (n < NN) {
            g_support[n * 32 + lane] = acc[m];
            float dv = g_dinv[n];
            __half2 h01 = __floats2half2_rn(acc[m].x * dv, acc[m].y * dv);
            __half2 h23 = __floats2half2_rn(acc[m].z * dv, acc[m].w * dv);
            g_ph[n * 32 + lane] = make_uint2(*(unsigned*)&h01, *(unsigned*)&h23);
        }
    }
}

// ---------------- fused layer-1 aggregate + ReLU + W2 dot ---------------------
// one warp per node; lane owns 4 features; neighbor gather in half2 (256B/edge)
__global__ void __launch_bounds__(256) k_agg(const float* __restrict__ W2,
                                             const float* __restrict__ b2) {
    int n = (int)((blockIdx.x * blockDim.x + threadIdx.x) >> 5);
    int lane = threadIdx.x & 31;
    if (n >= NN) return;

    float dn = g_dinv[n];
    float4 sv = g_support[n * 32 + lane];                  // exact self-loop
    float4 acc = make_float4(sv.x * dn, sv.y * dn, sv.z * dn, sv.w * dn);

    int start = g_off[n];
    int deg   = g_cnt[n];
    for (int base = 0; base < deg; base += 32) {
        int rem = deg - base;
        int cl = 0;
        if (lane < rem) cl = g_col[start + base + lane];   // coalesced chunk
        int lim = rem < 32 ? rem : 32;
        for (int i = 0; i < lim; i++) {
            int c = __shfl_sync(0xffffffffu, cl, i);
            uint2 v = __ldg(&g_ph[c * 32 + lane]);         // 256B/warp, coalesced
            float2 f01 = __half22float2(*(__half2*)&v.x);
            float2 f23 = __half22float2(*(__half2*)&v.y);
            acc.x += f01.x; acc.y += f01.y;
            acc.z += f23.x; acc.w += f23.y;
        }
    }

    float4 w2 = __ldg(&((const float4*)W2)[lane]);
    float h0 = fmaxf(acc.x * dn, 0.f), h1 = fmaxf(acc.y * dn, 0.f);
    float h2 = fmaxf(acc.z * dn, 0.f), h3 = fmaxf(acc.w * dn, 0.f);
    float p = h0 * w2.x + h1 * w2.y + h2 * w2.z + h3 * w2.w;
    #pragma unroll
    for (int o = 16; o; o >>= 1) p += __shfl_xor_sync(0xffffffffu, p, o);
    if (lane == 0) {
        float s = p + __ldg(b2);
        g_s[n]  = s;
        g_ds[n] = dn * s;
    }
}

// ---------------- layer 2 via CSR gather --------------------------------------
__global__ void __launch_bounds__(256) k_out(float* __restrict__ out) {
    int n = (int)((blockIdx.x * blockDim.x + threadIdx.x) >> 5);
    int lane = threadIdx.x & 31;
    if (n >= NN) return;
    int start = g_off[n];
    int deg   = g_cnt[n];
    float t = 0.f;
    for (int i = lane; i < deg; i += 32) t += g_ds[g_col[start + i]];
    #pragma unroll
    for (int o = 16; o; o >>= 1) t += __shfl_xor_sync(0xffffffffu, t, o);
    if (lane == 0) {
        float dn = g_dinv[n];
        out[n] = dn * (t + dn * g_s[n]);   // edges + self-loop
    }
}

// ---------------- launch -----------------------------------------------------
extern "C" void kernel_launch(void* const* d_in, const int* in_sizes, int n_in,
                              void* d_out, int out_size) {
    const float* x   = (const float*)d_in[0];
    const void*  ei  = d_in[1];                   // int32 or int64 [2, NE]
    const float* W1  = (const float*)d_in[2];
    const float* b1  = (const float*)d_in[3];
    const float* W2  = (const float*)d_in[4];
    const float* b2  = (const float*)d_in[5];
    float*       out = (float*)d_out;

    k_pre      <<<(NN + 255) / 256, 256>>>((const int*)ei);
    k_hist     <<<(NE + 255) / 256, 256>>>(ei);
    k_scan     <<<1, 1024>>>();
    k_scatter  <<<(NE + 255) / 256, 256>>>(ei);
    k_transpose<<<(DD * DD + 255) / 256, 256>>>(W1);
    k_gemm1    <<<(NN + 63) / 64, 256>>>(x, b1);
    k_agg      <<<(NN * 32 + 255) / 256, 256>>>(W2, b2);
    k_out      <<<(NN * 32 + 255) / 256, 256>>>(out);
}